// round 16
// baseline (speedup 1.0000x reference)
#include <cuda_runtime.h>
#include <float.h>

typedef unsigned long long U64;

// ---------------- scratch ----------------
#define D0_STRIDE 64012   // 64009 padded to mult of 4
#define D1_STRIDE 16132   // 16129 padded
__device__ float g_dist0[10 * D0_STRIDE];
__device__ float g_dist1[5 * D1_STRIDE];
__device__ float g_cand[384 * 5];
__device__ int   g_count;    // phase-1 barrier; reset by last CTA of phase 2
__device__ int   g_count2;   // phase-2 completion counter

#define NCTA 384

// ---------------- packed f32x2 helpers ----------------
__device__ __forceinline__ U64 add2(U64 a, U64 b) {
    U64 r; asm("add.rn.f32x2 %0, %1, %2;" : "=l"(r) : "l"(a), "l"(b)); return r;
}
__device__ __forceinline__ U64 pack2(float lo, float hi) {
    U64 r; asm("mov.b64 %0, {%1, %2};" : "=l"(r) : "f"(lo), "f"(hi)); return r;
}
__device__ __forceinline__ float2 unpack2(U64 v) {
    float lo, hi; asm("mov.b64 {%0, %1}, %2;" : "=f"(lo), "=f"(hi) : "l"(v));
    return make_float2(lo, hi);
}
#define ABS2_MASK 0x7FFFFFFF7FFFFFFFULL

// ---------------- sorted-5 insert + warp butterfly top-5 ----------------
__device__ __forceinline__ void ins5(float& a0, float& a1, float& a2, float& a3,
                                     float& a4, float v)
{
    if (v < a4) {
        a4 = v; float t;
        if (a4 < a3) { t = a3; a3 = a4; a4 = t; }
        if (a3 < a2) { t = a2; a2 = a3; a3 = t; }
        if (a2 < a1) { t = a1; a1 = a2; a2 = t; }
        if (a1 < a0) { t = a0; a0 = a1; a1 = t; }
    }
}

__device__ __forceinline__ void warpTop5(float& a0, float& a1, float& a2,
                                         float& a3, float& a4)
{
#pragma unroll
    for (int m = 16; m >= 1; m >>= 1) {
        float b0 = __shfl_xor_sync(0xffffffffu, a0, m);
        float b1 = __shfl_xor_sync(0xffffffffu, a1, m);
        float b2 = __shfl_xor_sync(0xffffffffu, a2, m);
        float b3 = __shfl_xor_sync(0xffffffffu, a3, m);
        float b4 = __shfl_xor_sync(0xffffffffu, a4, m);
        ins5(a0, a1, a2, a3, a4, b0);
        ins5(a0, a1, a2, a3, a4, b1);
        ins5(a0, a1, a2, a3, a4, b2);
        ins5(a0, a1, a2, a3, a4, b3);
        ins5(a0, a1, a2, a3, a4, b4);
    }
}

// =====================================================================
// Phase 2 (noinline: isolates register allocation from the dist loop).
// flat < 320 : dist0, target flat>>5, 32 chunks
// 320..379   : dist1, target 10+(flat-320)/12, 12 chunks
// 380..383   : idle (FLT_MAX candidates)
// Last CTA of g_count2 merges + writes scalar + resets counters.
// =====================================================================
__device__ __noinline__ void tail_phase(int flat, int tid, float* out)
{
    __shared__ float s_warp[8 * 5];
    __shared__ float s_partial[15];
    __shared__ int   s_last;

    const int wid  = tid >> 5;
    const int lane = tid & 31;

    float a0 = FLT_MAX, a1 = FLT_MAX, a2 = FLT_MAX, a3 = FLT_MAX, a4 = FLT_MAX;

    if (flat < 380) {
        const float* d; int n, nch, chunk;
        if (flat < 320) { d = g_dist0 + (flat >> 5) * D0_STRIDE; n = 64009;
                          nch = 32; chunk = flat & 31; }
        else            { int u = flat - 320;
                          d = g_dist1 + (u / 12) * D1_STRIDE; n = 16129;
                          nch = 12; chunk = u % 12; }

        const int n4  = n >> 2;
        const int gpc = (n4 + nch - 1) / nch;
        const int g0  = chunk * gpc;
        const int g1  = min(n4, g0 + gpc);
        const float4* d4 = (const float4*)d;

        for (int i = g0 + tid; i < g1; i += 256) {
            float4 v = d4[i];
            ins5(a0, a1, a2, a3, a4, v.x);
            ins5(a0, a1, a2, a3, a4, v.y);
            ins5(a0, a1, a2, a3, a4, v.z);
            ins5(a0, a1, a2, a3, a4, v.w);
        }
        if (chunk == 0 && tid == 0)                  // tail (n % 4 == 1)
            for (int j = n4 * 4; j < n; j++) ins5(a0, a1, a2, a3, a4, d[j]);
    }

    warpTop5(a0, a1, a2, a3, a4);
    if (lane < 5) {
        float v = (lane == 0) ? a0 : (lane == 1) ? a1 : (lane == 2) ? a2
                 : (lane == 3) ? a3 : a4;
        s_warp[wid * 5 + lane] = v;
    }
    __syncthreads();
    if (wid == 0) {
        a0 = (lane < 40) ? s_warp[lane] : FLT_MAX;
        a1 = FLT_MAX; a2 = FLT_MAX; a3 = FLT_MAX; a4 = FLT_MAX;
        float b1 = (lane + 32 < 40) ? s_warp[lane + 32] : FLT_MAX;
        ins5(a0, a1, a2, a3, a4, b1);
        warpTop5(a0, a1, a2, a3, a4);
        if (lane == 0) {
            float* c = g_cand + flat * 5;
            c[0] = a0; c[1] = a1; c[2] = a2; c[3] = a3; c[4] = a4;
        }
    }

    // -------- completion counter; last CTA merges --------
    __syncthreads();
    if (tid == 0) {
        __threadfence();
        int old = atomicAdd(&g_count2, 1);
        s_last = (old == NCTA - 1);
    }
    __syncthreads();
    if (!s_last) return;
    __threadfence();

    // warp w handles targets w and w+8
    for (int t = wid; t < 15; t += 8) {
        const float* c; int n2; float scale;
        if (t < 10) { c = g_cand + t * 160;               n2 = 160; scale = 1.0f / 28800.0f; }
        else        { c = g_cand + 1600 + (t - 10) * 60;  n2 = 60;  scale = 1.0f / 6400.0f; }

        float m0 = FLT_MAX, m1 = FLT_MAX, m2 = FLT_MAX, m3 = FLT_MAX, m4 = FLT_MAX;
        for (int j = lane; j < n2; j += 32)
            ins5(m0, m1, m2, m3, m4, __ldcg(c + j));
        warpTop5(m0, m1, m2, m3, m4);
        if (lane == 0)
            s_partial[t] = (m0 + m1 + m2 + m3 + m4) * scale;
    }
    __syncthreads();
    if (tid == 0) {
        float s = 0.f;
#pragma unroll
        for (int j = 0; j < 15; j++) s += s_partial[j];   // fixed order
        out[0] = s;
        g_count  = 0;          // reset for next graph replay
        g_count2 = 0;
    }
}

// =====================================================================
// dist kernel + grid barrier + fused tail. grid=(8,16,3), 256 threads.
// Single wave guaranteed: 384 CTAs <= 148*3 residency (launch_bounds).
// =====================================================================
#define TILE_W 32
#define TILE_H 16
#define SM_W 34
#define SM_H 18
#define SM_N (SM_W * SM_H)   // 612
#define TPG 5

__global__ __launch_bounds__(256, 3) void dist_kernel(
    const float* __restrict__ src0, const float* __restrict__ tgt0,
    const int* __restrict__ pos0,
    const float* __restrict__ src1, const float* __restrict__ tgt1,
    const int* __restrict__ pos1,
    float* __restrict__ out)
{
    __shared__ U64 s_negt[32 * TPG * 10];        // padded [cp][T][10]
    __shared__ U64 s_tile[2][SM_N];              // double-buffered tile

    const int tid  = threadIdx.x;
    const int sidx = blockIdx.y * 8 + blockIdx.x;          // 0..127
    const int flat = blockIdx.z * 128 + sidx;              // 0..383

    if (blockIdx.z == 2) {
        // ---------------- scale-1 (flat 256..319 active) ----------------
        if (sidx < 64) {
            U64* negt1 = s_negt;
            for (int i = tid; i < 64 * 5; i += 256) {
                int T = i % 5, cp = i / 5;
                int th = pos1[T * 2 + 0], tw = pos1[T * 2 + 1];
                const float* b = tgt1 + th * 128 + tw;
                negt1[i] = pack2(-b[(2 * cp) * 16384], -b[(2 * cp + 1) * 16384]);
            }
            __syncthreads();

            const int pp = sidx * 256 + tid;
            const int pc = pp < 16129 ? pp : 16128;   // clamp, keep thread alive
            const int h = pc / 127, w = pc - h * 127;
            const float* sp = src1 + h * 128 + w;

            U64 acc[5];
#pragma unroll
            for (int T = 0; T < 5; T++) acc[T] = 0ULL;

            for (int cp = 0; cp < 64; cp++) {
                U64 s = pack2(sp[(2 * cp) * 16384], sp[(2 * cp + 1) * 16384]);
#pragma unroll
                for (int T = 0; T < 5; T++) {
                    U64 d = add2(s, negt1[cp * 5 + T]) & ABS2_MASK;
                    acc[T] = add2(acc[T], d);
                }
            }
#pragma unroll
            for (int T = 0; T < 5; T++) {
                float2 a = unpack2(acc[T]);
                if (pp < 16129) g_dist1[T * D1_STRIDE + pp] = a.x + a.y;
            }
        }
    } else {
        // ---------------- scale-0 ----------------
        const int tx = blockIdx.x * TILE_W;
        const int ty = blockIdx.y * TILE_H;
        const int tb = blockIdx.z * TPG;

        for (int i = tid; i < 32 * TPG * 9; i += 256) {
            int o  = i % 9;
            int T  = (i / 9) % TPG;
            int cp = i / (9 * TPG);
            int th = pos0[(tb + T) * 2 + 0];
            int tw = pos0[(tb + T) * 2 + 1];
            int di = o / 3, dj = o % 3;
            const float* b = tgt0 + (th + di) * 256 + (tw + dj);
            s_negt[cp * (TPG * 10) + T * 10 + o] =
                pack2(-b[(2 * cp) * 65536], -b[(2 * cp + 1) * 65536]);
        }

        int  goff[3];
        bool gval[3];
#pragma unroll
        for (int k = 0; k < 3; k++) {
            int i = tid + k * 256;
            int r = i / SM_W, c = i - r * SM_W;
            int y = ty + r, x = tx + c;
            gval[k] = (i < SM_N) && (y < 256) && (x < 256);
            goff[k] = y * 256 + x;
        }

        U64 pre[3];
        {   // prologue: cp = 0 -> buf 0
#pragma unroll
            for (int k = 0; k < 3; k++)
                pre[k] = gval[k] ? pack2(src0[goff[k]], src0[goff[k] + 65536]) : 0ULL;
#pragma unroll
            for (int k = 0; k < 3; k++) {
                int i = tid + k * 256;
                if (i < SM_N) s_tile[0][i] = pre[k];
            }
        }
        __syncthreads();

        const int thx = tid & 31;
        const int thy = tid >> 5;
        const int w  = tx + thx;
        const int h0 = ty + 2 * thy;
        const bool act0 = (w < 253) && (h0 < 253);
        const bool act1 = (w < 253) && (h0 + 1 < 253);
        const int r0 = 2 * thy;

        U64 acc0[TPG], acc1[TPG];
#pragma unroll
        for (int T = 0; T < TPG; T++) { acc0[T] = 0ULL; acc1[T] = 0ULL; }

        for (int cp = 0; cp < 32; cp++) {
            if (cp + 1 < 32) {
                const float* s = src0 + (2 * (cp + 1)) * 65536;
#pragma unroll
                for (int k = 0; k < 3; k++)
                    pre[k] = gval[k] ? pack2(s[goff[k]], s[goff[k] + 65536]) : 0ULL;
            }

            const U64* buf = s_tile[cp & 1];
            U64 sv[4][3];
#pragma unroll
            for (int r = 0; r < 4; r++)
#pragma unroll
                for (int j = 0; j < 3; j++)
                    sv[r][j] = buf[(r0 + r) * SM_W + thx + j];

            const U64* tp = s_negt + cp * (TPG * 10);
#pragma unroll
            for (int T = 0; T < TPG; T++) {
                const ulonglong2* tp2 = (const ulonglong2*)(tp + T * 10);
#pragma unroll
                for (int o2 = 0; o2 < 4; o2++) {
                    ulonglong2 q = tp2[o2];
                    {
                        const int o = 2 * o2, di = o / 3, dj = o % 3;
                        U64 d0 = add2(sv[di][dj],     q.x) & ABS2_MASK;
                        U64 d1 = add2(sv[di + 1][dj], q.x) & ABS2_MASK;
                        acc0[T] = add2(acc0[T], d0);
                        acc1[T] = add2(acc1[T], d1);
                    }
                    {
                        const int o = 2 * o2 + 1, di = o / 3, dj = o % 3;
                        U64 d0 = add2(sv[di][dj],     q.y) & ABS2_MASK;
                        U64 d1 = add2(sv[di + 1][dj], q.y) & ABS2_MASK;
                        acc0[T] = add2(acc0[T], d0);
                        acc1[T] = add2(acc1[T], d1);
                    }
                }
                {   // o = 8
                    U64 nt = tp[T * 10 + 8];
                    U64 d0 = add2(sv[2][2], nt) & ABS2_MASK;
                    U64 d1 = add2(sv[3][2], nt) & ABS2_MASK;
                    acc0[T] = add2(acc0[T], d0);
                    acc1[T] = add2(acc1[T], d1);
                }
            }

            if (cp + 1 < 32) {
                U64* nb = s_tile[(cp + 1) & 1];
#pragma unroll
                for (int k = 0; k < 3; k++) {
                    int i = tid + k * 256;
                    if (i < SM_N) nb[i] = pre[k];
                }
                __syncthreads();
            }
        }

#pragma unroll
        for (int T = 0; T < TPG; T++) {
            float2 a0 = unpack2(acc0[T]);
            float2 a1 = unpack2(acc1[T]);
            if (act0) g_dist0[(tb + T) * D0_STRIDE + h0 * 253 + w]       = a0.x + a0.y;
            if (act1) g_dist0[(tb + T) * D0_STRIDE + (h0 + 1) * 253 + w] = a1.x + a1.y;
        }
    }

    // ---------------- grid-wide barrier (single wave: 384 <= 444) ----------------
    __syncthreads();                       // CTA writes done
    if (tid == 0) {
        __threadfence();                   // publish this CTA's stores
        atomicAdd(&g_count, 1);
        while (*(volatile int*)&g_count < NCTA)
            __nanosleep(128);
    }
    __syncthreads();
    __threadfence();                       // acquire all CTAs' stores

    tail_phase(flat, tid, out);
}

// =====================================================================
extern "C" void kernel_launch(void* const* d_in, const int* in_sizes, int n_in,
                              void* d_out, int out_size)
{
    const float* src0 = (const float*)d_in[0];
    const float* tgt0 = (const float*)d_in[1];
    const float* src1 = (const float*)d_in[2];
    const float* tgt1 = (const float*)d_in[3];
    const int*   pos0 = (const int*)d_in[4];
    const int*   pos1 = (const int*)d_in[5];

    dim3 g(8, 16, 3);
    dist_kernel<<<g, 256>>>(src0, tgt0, pos0, src1, tgt1, pos1, (float*)d_out);
}

// round 17
// speedup vs baseline: 1.1085x; 1.1085x over previous
#include <cuda_runtime.h>
#include <float.h>

typedef unsigned long long U64;

// ---------------- scratch ----------------
#define D0_STRIDE 64012   // 64009 padded to mult of 4
#define D1_STRIDE 16132   // 16129 padded
__device__ float g_dist0[10 * D0_STRIDE];
__device__ float g_dist1[5 * D1_STRIDE];
__device__ float g_cand[180 * 5];
__device__ int   g_count;              // zero-init; self-reset each replay

// ---------------- packed f32x2 helpers ----------------
__device__ __forceinline__ U64 add2(U64 a, U64 b) {
    U64 r; asm("add.rn.f32x2 %0, %1, %2;" : "=l"(r) : "l"(a), "l"(b)); return r;
}
__device__ __forceinline__ U64 pack2(float lo, float hi) {
    U64 r; asm("mov.b64 %0, {%1, %2};" : "=l"(r) : "f"(lo), "f"(hi)); return r;
}
__device__ __forceinline__ float2 unpack2(U64 v) {
    float lo, hi; asm("mov.b64 {%0, %1}, %2;" : "=f"(lo), "=f"(hi) : "l"(v));
    return make_float2(lo, hi);
}
#define ABS2_MASK 0x7FFFFFFF7FFFFFFFULL

// =====================================================================
// dist kernel: barrier-free scale-0 core. Per-thread windows loaded
// directly from global (L1-served, immediate-offset LDGs); no shared
// tile, no per-cp __syncthreads.
//   grid = (8, 16, 3), 256 threads
//   z in {0,1}: scale0 (C=64,H=W=256,ps=3,Hm=253), 5 targets per z
//   z == 2   : scale1 (C=128,H=W=128,ps=1,Hm=127), flat CTA < 64
// =====================================================================
#define TILE_W 32
#define TILE_H 16
#define TPG 5

__global__ __launch_bounds__(256, 3) void dist_kernel(
    const float* __restrict__ src0, const float* __restrict__ tgt0,
    const int* __restrict__ pos0,
    const float* __restrict__ src1, const float* __restrict__ tgt1,
    const int* __restrict__ pos1)
{
    __shared__ U64 s_negt[32 * TPG * 10];        // padded [cp][T][10]

    const int tid = threadIdx.x;

    // ---------------- scale-1 branch ----------------
    if (blockIdx.z == 2) {
        const int flat = blockIdx.y * 8 + blockIdx.x;
        if (flat >= 64) return;
        U64* negt1 = s_negt;
        for (int i = tid; i < 64 * 5; i += 256) {
            int T = i % 5, cp = i / 5;
            int th = pos1[T * 2 + 0], tw = pos1[T * 2 + 1];
            const float* b = tgt1 + th * 128 + tw;
            negt1[i] = pack2(-b[(2 * cp) * 16384], -b[(2 * cp + 1) * 16384]);
        }
        __syncthreads();

        const int pp = flat * 256 + tid;
        if (pp >= 16129) return;
        const int h = pp / 127, w = pp - h * 127;
        const float* sp = src1 + h * 128 + w;

        U64 acc[5];
#pragma unroll
        for (int T = 0; T < 5; T++) acc[T] = 0ULL;

        for (int cp = 0; cp < 64; cp++) {
            U64 s = pack2(sp[(2 * cp) * 16384], sp[(2 * cp + 1) * 16384]);
#pragma unroll
            for (int T = 0; T < 5; T++) {
                U64 d = add2(s, negt1[cp * 5 + T]) & ABS2_MASK;
                acc[T] = add2(acc[T], d);
            }
        }
#pragma unroll
        for (int T = 0; T < 5; T++) {
            float2 a = unpack2(acc[T]);
            g_dist1[T * D1_STRIDE + pp] = a.x + a.y;
        }
        return;
    }

    // ---------------- scale-0 branch ----------------
    const int tx = blockIdx.x * TILE_W;
    const int ty = blockIdx.y * TILE_H;
    const int tb = blockIdx.z * TPG;

    for (int i = tid; i < 32 * TPG * 9; i += 256) {
        int o  = i % 9;
        int T  = (i / 9) % TPG;
        int cp = i / (9 * TPG);
        int th = pos0[(tb + T) * 2 + 0];
        int tw = pos0[(tb + T) * 2 + 1];
        int di = o / 3, dj = o % 3;
        const float* b = tgt0 + (th + di) * 256 + (tw + dj);
        s_negt[cp * (TPG * 10) + T * 10 + o] =
            pack2(-b[(2 * cp) * 65536], -b[(2 * cp + 1) * 65536]);
    }
    __syncthreads();                 // the ONLY barrier in this branch

    const int thx = tid & 31;
    const int thy = tid >> 5;
    const int w  = tx + thx;
    const int h0 = ty + 2 * thy;
    const bool act0 = (w < 253) && (h0 < 253);
    const bool act1 = (w < 253) && (h0 + 1 < 253);

    // Clamped window origin: perturbs only lanes whose results are discarded.
    const int wx = min(w, 253);
    const int hy = min(h0, 252);

    // 4 row pointers; column/channel offsets are LDG immediates.
    const float* p0 = src0 + (hy + 0) * 256 + wx;
    const float* p1 = src0 + (hy + 1) * 256 + wx;
    const float* p2 = src0 + (hy + 2) * 256 + wx;
    const float* p3 = src0 + (hy + 3) * 256 + wx;

    U64 acc0[TPG], acc1[TPG];
#pragma unroll
    for (int T = 0; T < TPG; T++) { acc0[T] = 0ULL; acc1[T] = 0ULL; }

    for (int cp = 0; cp < 32; cp++) {
        // load 4x3 window for both channels of this pair (L1-served)
        U64 sv[4][3];
#pragma unroll
        for (int j = 0; j < 3; j++) {
            sv[0][j] = pack2(p0[j], p0[65536 + j]);
            sv[1][j] = pack2(p1[j], p1[65536 + j]);
            sv[2][j] = pack2(p2[j], p2[65536 + j]);
            sv[3][j] = pack2(p3[j], p3[65536 + j]);
        }
        p0 += 131072; p1 += 131072; p2 += 131072; p3 += 131072;

        const U64* tp = s_negt + cp * (TPG * 10);
#pragma unroll
        for (int T = 0; T < TPG; T++) {
            const ulonglong2* tp2 = (const ulonglong2*)(tp + T * 10);
#pragma unroll
            for (int o2 = 0; o2 < 4; o2++) {
                ulonglong2 q = tp2[o2];
                {
                    const int o = 2 * o2, di = o / 3, dj = o % 3;
                    U64 d0 = add2(sv[di][dj],     q.x) & ABS2_MASK;
                    U64 d1 = add2(sv[di + 1][dj], q.x) & ABS2_MASK;
                    acc0[T] = add2(acc0[T], d0);
                    acc1[T] = add2(acc1[T], d1);
                }
                {
                    const int o = 2 * o2 + 1, di = o / 3, dj = o % 3;
                    U64 d0 = add2(sv[di][dj],     q.y) & ABS2_MASK;
                    U64 d1 = add2(sv[di + 1][dj], q.y) & ABS2_MASK;
                    acc0[T] = add2(acc0[T], d0);
                    acc1[T] = add2(acc1[T], d1);
                }
            }
            {   // o = 8
                U64 nt = tp[T * 10 + 8];
                U64 d0 = add2(sv[2][2], nt) & ABS2_MASK;
                U64 d1 = add2(sv[3][2], nt) & ABS2_MASK;
                acc0[T] = add2(acc0[T], d0);
                acc1[T] = add2(acc1[T], d1);
            }
        }
    }

#pragma unroll
    for (int T = 0; T < TPG; T++) {
        float2 a0 = unpack2(acc0[T]);
        float2 a1 = unpack2(acc1[T]);
        if (act0) g_dist0[(tb + T) * D0_STRIDE + h0 * 253 + w]       = a0.x + a0.y;
        if (act1) g_dist0[(tb + T) * D0_STRIDE + (h0 + 1) * 253 + w] = a1.x + a1.y;
    }
}

// =====================================================================
// topk: 180 CTAs x 256 (benched-best R6 variant). bx<160: t=bx/16,
// 16 chunks over dist0. bx>=160: t=10+(bx-160)/4, 4 chunks over dist1.
// Per-CTA top5 -> g_cand[bx*5]; last CTA merges and writes the scalar.
// =====================================================================
__device__ __forceinline__ void ins5(float& a0, float& a1, float& a2, float& a3,
                                     float& a4, float v)
{
    if (v < a4) {
        a4 = v; float t;
        if (a4 < a3) { t = a3; a3 = a4; a4 = t; }
        if (a3 < a2) { t = a2; a2 = a3; a3 = t; }
        if (a2 < a1) { t = a1; a1 = a2; a2 = t; }
        if (a1 < a0) { t = a0; a0 = a1; a1 = t; }
    }
}

__device__ __forceinline__ void warpTop5(float& a0, float& a1, float& a2,
                                         float& a3, float& a4)
{
#pragma unroll
    for (int m = 16; m >= 1; m >>= 1) {
        float b0 = __shfl_xor_sync(0xffffffffu, a0, m);
        float b1 = __shfl_xor_sync(0xffffffffu, a1, m);
        float b2 = __shfl_xor_sync(0xffffffffu, a2, m);
        float b3 = __shfl_xor_sync(0xffffffffu, a3, m);
        float b4 = __shfl_xor_sync(0xffffffffu, a4, m);
        ins5(a0, a1, a2, a3, a4, b0);
        ins5(a0, a1, a2, a3, a4, b1);
        ins5(a0, a1, a2, a3, a4, b2);
        ins5(a0, a1, a2, a3, a4, b3);
        ins5(a0, a1, a2, a3, a4, b4);
    }
}

#define NCTA_TOPK 180

__global__ __launch_bounds__(256) void topk_kernel(float* __restrict__ out)
{
    __shared__ float s_warp[8 * 5];
    __shared__ float s_partial[15];
    __shared__ int   s_last;

    const int bx   = blockIdx.x;
    const int tid  = threadIdx.x;
    const int wid  = tid >> 5;
    const int lane = tid & 31;

    const float* d;
    int n, nchunks, chunk;
    if (bx < 160) { chunk = bx & 15; nchunks = 16;
                    d = g_dist0 + (bx >> 4) * D0_STRIDE; n = 64009; }
    else          { chunk = (bx - 160) & 3; nchunks = 4;
                    d = g_dist1 + ((bx - 160) >> 2) * D1_STRIDE; n = 16129; }

    const int n4  = n >> 2;
    const int gpc = (n4 + nchunks - 1) / nchunks;
    const int g0  = chunk * gpc;
    const int g1  = min(n4, g0 + gpc);
    const float4* d4 = (const float4*)d;

    float a0 = FLT_MAX, a1 = FLT_MAX, a2 = FLT_MAX, a3 = FLT_MAX, a4 = FLT_MAX;
    for (int i = g0 + tid; i < g1; i += 256) {
        float4 v = d4[i];
        ins5(a0, a1, a2, a3, a4, v.x);
        ins5(a0, a1, a2, a3, a4, v.y);
        ins5(a0, a1, a2, a3, a4, v.z);
        ins5(a0, a1, a2, a3, a4, v.w);
    }
    if (chunk == 0 && tid == 0)                      // tail (n % 4 == 1)
        for (int j = n4 * 4; j < n; j++) ins5(a0, a1, a2, a3, a4, d[j]);

    warpTop5(a0, a1, a2, a3, a4);
    if (lane < 5) {
        float v = (lane == 0) ? a0 : (lane == 1) ? a1 : (lane == 2) ? a2
                 : (lane == 3) ? a3 : a4;
        s_warp[wid * 5 + lane] = v;
    }
    __syncthreads();
    if (wid == 0) {
        a0 = (lane < 40) ? s_warp[lane] : FLT_MAX;
        a1 = FLT_MAX; a2 = FLT_MAX; a3 = FLT_MAX; a4 = FLT_MAX;
        float b1 = (lane + 32 < 40) ? s_warp[lane + 32] : FLT_MAX;
        ins5(a0, a1, a2, a3, a4, b1);
        warpTop5(a0, a1, a2, a3, a4);
        if (lane == 0) {
            float* c = g_cand + bx * 5;
            c[0] = a0; c[1] = a1; c[2] = a2; c[3] = a3; c[4] = a4;
        }
    }

    // ---------------- last-CTA merge ----------------
    if (tid == 0) {
        __threadfence();
        int old = atomicAdd(&g_count, 1);
        s_last = (old == NCTA_TOPK - 1);
        if (s_last) g_count = 0;                    // reset for next replay
    }
    __syncthreads();
    if (!s_last) return;
    __threadfence();

    // warp w handles targets w and w+8
    for (int t = wid; t < 15; t += 8) {
        const float* c; int n2; float scale;
        if (t < 10) { c = g_cand + t * 80;              n2 = 80; scale = 1.0f / 28800.0f; }
        else        { c = g_cand + 800 + (t - 10) * 20; n2 = 20; scale = 1.0f / 6400.0f; }

        float m0 = FLT_MAX, m1 = FLT_MAX, m2 = FLT_MAX, m3 = FLT_MAX, m4 = FLT_MAX;
        for (int j = lane; j < n2; j += 32)
            ins5(m0, m1, m2, m3, m4, __ldcg(c + j));
        warpTop5(m0, m1, m2, m3, m4);
        if (lane == 0)
            s_partial[t] = (m0 + m1 + m2 + m3 + m4) * scale;
    }
    __syncthreads();
    if (tid == 0) {
        float s = 0.f;
#pragma unroll
        for (int j = 0; j < 15; j++) s += s_partial[j];
        out[0] = s;
    }
}

// =====================================================================
extern "C" void kernel_launch(void* const* d_in, const int* in_sizes, int n_in,
                              void* d_out, int out_size)
{
    const float* src0 = (const float*)d_in[0];
    const float* tgt0 = (const float*)d_in[1];
    const float* src1 = (const float*)d_in[2];
    const float* tgt1 = (const float*)d_in[3];
    const int*   pos0 = (const int*)d_in[4];
    const int*   pos1 = (const int*)d_in[5];

    dim3 g(8, 16, 3);
    dist_kernel<<<g, 256>>>(src0, tgt0, pos0, src1, tgt1, pos1);
    topk_kernel<<<NCTA_TOPK, 256>>>((float*)d_out);
}